// round 1
// baseline (speedup 1.0000x reference)
#include <cuda_runtime.h>

// Problem constants (fixed by the dataset: x [256,2048,7,7], x0 [256,49,1])
#define BATCH   256
#define CDIM    2048
#define NDIM    49          // H*W = 7*7
#define TSZ     7           // tile size (7x7 tiles of the 49x49 Gram matrix)
#define CHUNK   32          // C rows per smem chunk
#define NSPLIT  8           // C-splits per tile
#define NTILES  28          // upper-triangular 7x7 tile pairs
#define THREADS 224         // 28 tiles * 8 splits = 7 warps
#define NCHUNK  (CDIM / CHUNK)          // 64
#define CHUNK_ELEMS (CHUNK * NDIM)      // 1568 == THREADS * 7
#define EPSV    1e-12f

// tile index -> (ti, tj), ti <= tj
__constant__ int c_ti[NTILES] = {0,0,0,0,0,0,0, 1,1,1,1,1,1, 2,2,2,2,2, 3,3,3,3, 4,4,4, 5,5, 6};
__constant__ int c_tj[NTILES] = {0,1,2,3,4,5,6, 1,2,3,4,5,6, 2,3,4,5,6, 3,4,5,6, 4,5,6, 5,6, 6};

// per-batch penalty scratch (no allocation allowed -> device global)
__device__ float g_penalty[BATCH];

// Block-wide sum over the first 49 lanes' values (all THREADS threads call this).
__device__ __forceinline__ float reduce49(float v, int t, float* sarr) {
    if (t < 64) sarr[t] = (t < NDIM) ? v : 0.0f;
    __syncthreads();
    if (t < 32) {
        float r = sarr[t] + sarr[t + 32];
        r += __shfl_xor_sync(0xffffffffu, r, 16);
        r += __shfl_xor_sync(0xffffffffu, r, 8);
        r += __shfl_xor_sync(0xffffffffu, r, 4);
        r += __shfl_xor_sync(0xffffffffu, r, 2);
        r += __shfl_xor_sync(0xffffffffu, r, 1);
        if (t == 0) sarr[0] = r;
    }
    __syncthreads();
    float out = sarr[0];
    __syncthreads();   // protect sarr[0] from the next reduce's writes
    return out;
}

__global__ void __launch_bounds__(THREADS)
ofpenalty_kernel(const float* __restrict__ x, const float* __restrict__ x0) {
    __shared__ float sbuf[2][CHUNK_ELEMS];   // streamed W chunks
    __shared__ float sA[NDIM * NDIM];        // Gram matrix
    __shared__ float sx[NDIM];               // power-iteration vector
    __shared__ float sred[64];

    const int t     = threadIdx.x;
    const int b     = blockIdx.x;
    const int tile  = t >> 3;
    const int split = t & 7;
    const int ti = c_ti[tile] * TSZ;
    const int tj = c_tj[tile] * TSZ;
    const float* __restrict__ xb = x + (size_t)b * (CDIM * NDIM);

    float acc[TSZ * TSZ];
#pragma unroll
    for (int k = 0; k < TSZ * TSZ; k++) acc[k] = 0.0f;

    // ---- load chunk 0 ----
#pragma unroll
    for (int i = 0; i < 7; i++) sbuf[0][t + i * THREADS] = xb[t + i * THREADS];
    __syncthreads();

    // ---- streamed Gram accumulation (double-buffered) ----
    for (int ch = 0; ch < NCHUNK; ch++) {
        const int cur = ch & 1;

        // register prefetch of next chunk (1568 = 224*7, fully covered)
        float pre[7];
        if (ch + 1 < NCHUNK) {
            const float* __restrict__ src = xb + (size_t)(ch + 1) * CHUNK_ELEMS;
#pragma unroll
            for (int i = 0; i < 7; i++) pre[i] = __ldg(src + t + i * THREADS);
        }

        // 7x7 outer-product accumulation over this thread's C-slice
#pragma unroll
        for (int cc = 0; cc < CHUNK / NSPLIT; cc++) {
            const float* __restrict__ row = &sbuf[cur][(cc * NSPLIT + split) * NDIM];
            float av[TSZ], bv[TSZ];
#pragma unroll
            for (int k = 0; k < TSZ; k++) av[k] = row[ti + k];
#pragma unroll
            for (int k = 0; k < TSZ; k++) bv[k] = row[tj + k];
#pragma unroll
            for (int i = 0; i < TSZ; i++)
#pragma unroll
                for (int j = 0; j < TSZ; j++)
                    acc[i * TSZ + j] = fmaf(av[i], bv[j], acc[i * TSZ + j]);
        }

        if (ch + 1 < NCHUNK) {
            const int nxt = cur ^ 1;
#pragma unroll
            for (int i = 0; i < 7; i++) sbuf[nxt][t + i * THREADS] = pre[i];
        }
        __syncthreads();
    }

    // ---- reduce the 8 C-splits (lanes t&7) via butterfly shuffles ----
#pragma unroll
    for (int k = 0; k < TSZ * TSZ; k++) {
        acc[k] += __shfl_xor_sync(0xffffffffu, acc[k], 4);
        acc[k] += __shfl_xor_sync(0xffffffffu, acc[k], 2);
        acc[k] += __shfl_xor_sync(0xffffffffu, acc[k], 1);
    }
    if (split == 0) {
#pragma unroll
        for (int i = 0; i < TSZ; i++)
#pragma unroll
            for (int j = 0; j < TSZ; j++) {
                const float v = acc[i * TSZ + j];
                sA[(ti + i) * NDIM + (tj + j)] = v;   // upper
                sA[(tj + j) * NDIM + (ti + i)] = v;   // mirror (diag writes twice)
            }
    }
    if (t < NDIM) sx[t] = x0[b * NDIM + t];
    __syncthreads();

    // ---- power iteration 1: largest eigenvalue of ATA ----
    for (int it = 0; it < 9; it++) {
        float y = 0.0f;
        if (t < NDIM) {
#pragma unroll
            for (int m = 0; m < NDIM; m++) y = fmaf(sA[t * NDIM + m], sx[m], y);
        }
        const float n2  = reduce49(y * y, t, sred);
        const float nrm = fmaxf(sqrtf(n2), EPSV);
        if (t < NDIM) sx[t] = y / nrm;
        __syncthreads();
    }
    float y = 0.0f, xv = 0.0f;
    if (t < NDIM) {
        xv = sx[t];
#pragma unroll
        for (int m = 0; m < NDIM; m++) y = fmaf(sA[t * NDIM + m], sx[m], y);
    }
    float num = reduce49(y * xv, t, sred);
    float den = reduce49(xv * xv, t, sred);
    const float largest = num / den;

    // ---- power iteration 2 on shifted matrix (ATA - largest*I), warm start x1 ----
    for (int it = 0; it < 9; it++) {
        float ys = 0.0f;
        if (t < NDIM) {
#pragma unroll
            for (int m = 0; m < NDIM; m++) ys = fmaf(sA[t * NDIM + m], sx[m], ys);
            ys -= largest * sx[t];
        }
        const float n2  = reduce49(ys * ys, t, sred);
        const float nrm = fmaxf(sqrtf(n2), EPSV);
        if (t < NDIM) sx[t] = ys / nrm;
        __syncthreads();
    }
    y = 0.0f; xv = 0.0f;
    if (t < NDIM) {
        xv = sx[t];
#pragma unroll
        for (int m = 0; m < NDIM; m++) y = fmaf(sA[t * NDIM + m], sx[m], y);
        y -= largest * xv;
    }
    num = reduce49(y * xv, t, sred);
    den = reduce49(xv * xv, t, sred);
    const float tmp      = num / den;
    const float smallest = tmp + largest;

    if (t == 0) {
        const float r = largest / smallest - 1.0f;
        g_penalty[b] = r * r;   // BETA = 1
    }
}

// Deterministic final reduction: sum(penalty)/B
__global__ void ofpenalty_finalize(float* __restrict__ out) {
    __shared__ float s[BATCH];
    const int t = threadIdx.x;
    s[t] = g_penalty[t];
    __syncthreads();
#pragma unroll
    for (int off = BATCH / 2; off > 0; off >>= 1) {
        if (t < off) s[t] += s[t + off];
        __syncthreads();
    }
    if (t == 0) out[0] = s[0] * (1.0f / (float)BATCH);
}

extern "C" void kernel_launch(void* const* d_in, const int* in_sizes, int n_in,
                              void* d_out, int out_size) {
    const float* x  = (const float*)d_in[0];   // [256, 2048, 7, 7]
    const float* x0 = (const float*)d_in[1];   // [256, 49, 1]
    float* out = (float*)d_out;

    ofpenalty_kernel<<<BATCH, THREADS>>>(x, x0);
    ofpenalty_finalize<<<1, BATCH>>>(out);
}